// round 16
// baseline (speedup 1.0000x reference)
#include <cuda_runtime.h>
#include <cuda_bf16.h>
#include <cuda_fp16.h>
#include <math.h>

#define DM 768
#define NH 12
#define DH 64
#define BB 4
#define TT 2048
#define MROWS (BB*TT)   // 8192
#define ZSZ ((size_t)BB*NH*TT*DH)   // per-tensor q/k/v elems

// ---------------- scratch (device globals; no allocation allowed) ----------
// all arrays hold raw fp16 bits
__device__ unsigned short g_xh[(size_t)MROWS*DM];
__device__ unsigned short g_wh[4*(size_t)DM*DM];
__device__ unsigned short g_h3[3*ZSZ];              // q (scaled), k, v — fp16 single
__device__ unsigned short g_yh[(size_t)MROWS*DM];

// ---------------- helpers --------------------------------------------------
__device__ __forceinline__ float ex2(float x) {
    float r; asm("ex2.approx.f32 %0, %1;" : "=f"(r) : "f"(x)); return r;
}
__device__ __forceinline__ unsigned ex2h2(unsigned x) {
    unsigned r; asm("ex2.approx.f16x2 %0, %1;" : "=r"(r) : "r"(x)); return r;
}
// fp16 m16n8k16
__device__ __forceinline__ void mma16h(float d[4],
                                       unsigned a0, unsigned a1, unsigned a2, unsigned a3,
                                       unsigned b0, unsigned b1) {
    asm volatile(
        "mma.sync.aligned.m16n8k16.row.col.f32.f16.f16.f32 "
        "{%0,%1,%2,%3}, {%4,%5,%6,%7}, {%8,%9}, {%0,%1,%2,%3};\n"
        : "+f"(d[0]), "+f"(d[1]), "+f"(d[2]), "+f"(d[3])
        : "r"(a0), "r"(a1), "r"(a2), "r"(a3), "r"(b0), "r"(b1));
}
__device__ __forceinline__ void ldm4(unsigned r[4], unsigned addr) {
    asm volatile("ldmatrix.sync.aligned.m8n8.x4.shared.b16 {%0,%1,%2,%3}, [%4];"
                 : "=r"(r[0]), "=r"(r[1]), "=r"(r[2]), "=r"(r[3]) : "r"(addr));
}
__device__ __forceinline__ void ldm4t(unsigned r[4], unsigned addr) {
    asm volatile("ldmatrix.sync.aligned.m8n8.x4.trans.shared.b16 {%0,%1,%2,%3}, [%4];"
                 : "=r"(r[0]), "=r"(r[1]), "=r"(r[2]), "=r"(r[3]) : "r"(addr));
}
__device__ __forceinline__ unsigned s2u(const void* p) {
    return (unsigned)__cvta_generic_to_shared(p);
}
__device__ __forceinline__ void cp16(unsigned saddr, const void* gptr) {
    asm volatile("cp.async.cg.shared.global [%0], [%1], 16;"
                 :: "r"(saddr), "l"(gptr) : "memory");
}
__device__ __forceinline__ void cp_commit() {
    asm volatile("cp.async.commit_group;" ::: "memory");
}
template<int N>
__device__ __forceinline__ void cp_wait() {
    asm volatile("cp.async.wait_group %0;" :: "n"(N) : "memory");
}
__device__ __forceinline__ unsigned packh2(float x0, float x1) {
    __half2 t = __floats2half2_rn(x0, x1);
    return *reinterpret_cast<unsigned*>(&t);
}
__device__ __forceinline__ __half2 u2h2(unsigned u) {
    return *reinterpret_cast<__half2*>(&u);
}
__device__ __forceinline__ unsigned h2u(__half2 h) {
    return *reinterpret_cast<unsigned*>(&h);
}

// ---------------- pre-pass converts ----------------------------------------
// x -> fp16 single
__global__ void convert_x(const float* __restrict__ src,
                          unsigned short* __restrict__ h, int n4)
{
    int i = blockIdx.x * blockDim.x + threadIdx.x;
    if (i >= n4) return;
    float4 v = reinterpret_cast<const float4*>(src)[i];
    reinterpret_cast<unsigned*>(h)[2*i]   = packh2(v.x, v.y);
    reinterpret_cast<unsigned*>(h)[2*i+1] = packh2(v.z, v.w);
}
// 4 weights -> fp16 single (blockIdx.y selects matrix)
__global__ void convert_w4(const float* __restrict__ s0, const float* __restrict__ s1,
                           const float* __restrict__ s2, const float* __restrict__ s3,
                           unsigned short* __restrict__ h, int n4)
{
    int i = blockIdx.x * blockDim.x + threadIdx.x;
    if (i >= n4) return;
    const int z = blockIdx.y;
    const float* src = (z == 0) ? s0 : ((z == 1) ? s1 : ((z == 2) ? s2 : s3));
    const size_t off2 = (size_t)z * (DM * DM / 2);
    float4 v = reinterpret_cast<const float4*>(src)[i];
    reinterpret_cast<unsigned*>(h)[off2 + 2*i]   = packh2(v.x, v.y);
    reinterpret_cast<unsigned*>(h)[off2 + 2*i+1] = packh2(v.z, v.w);
}

// ---------------------------------------------------------------------------
// fp16 1-mma GEMM (mma.sync), BK=32, 3-stage cp.async, ONE barrier per iter.
// MODE 0 (QKV): BM=128, BN=128, 8 warps 2m x 4n; z=0->Q(*QSCALE),1->K,2->V.
// MODE 1 (proj): BM=128, BN=64, 8 warps 4m x 2n (finer tiles kill tail waste);
//                fp32 out.
// smem row stride 40 halves (conflict-free ldmatrix / STS).
// ---------------------------------------------------------------------------
#define HST2 40
#define AB2  (128*HST2*2)      // 10240 A bytes (both modes)
#define QSCALE (0.125f * 1.4426950408889634f)

template<int MODE>
__global__ __launch_bounds__(256, 2)
void gemm_f16(const unsigned short* __restrict__ Ah,
              const unsigned short* __restrict__ Whb,
              const float* __restrict__ b0p, const float* __restrict__ b1p,
              const float* __restrict__ b2p,
              unsigned short* __restrict__ ChB,
              float* __restrict__ outF)
{
    constexpr int NT  = (MODE == 1) ? 64 : 128;     // BN
    constexpr int MI  = (MODE == 1) ? 2 : 4;        // m16 tiles per warp
    constexpr int BB2 = NT * HST2 * 2;              // B bytes
    constexpr int GSTG = AB2 + BB2;

    extern __shared__ __align__(16) char gsm[];
    const unsigned sbase = s2u(gsm);

    const int z = blockIdx.z;
    const int widx = (MODE == 1) ? 3 : z;
    const size_t woff = (size_t)widx * DM * DM;
    const float* bias = (MODE == 1) ? b0p : ((z == 0) ? b0p : ((z == 1) ? b1p : b2p));

    const int tid  = threadIdx.x;
    const int lane = tid & 31;
    const int wid  = tid >> 5;
    const int m0 = blockIdx.y * 128;
    const int n0 = blockIdx.x * NT;
    const int wm = (MODE == 1) ? (wid >> 1) : (wid >> 2);
    const int wn = (MODE == 1) ? (wid & 1)  : (wid & 3);
    const int g  = lane >> 2;
    const int c  = lane & 3;

    const int rowA_ = (lane & 7) + ((lane >> 3) & 1) * 8;
    const int colA_ = (lane >> 4) * 8;
    const int rowB_ = (lane & 7) + ((lane >> 4) & 1) * 8;
    const int colB_ = ((lane >> 3) & 1) * 8;

    // loader: thread -> row = tid>>1, k-half = (tid&1)*16 halves (32B)
    const int lrow  = tid >> 1;
    const int lkoff = (tid & 1) * 16;          // halves
    const unsigned short* pa = Ah + (size_t)(m0 + lrow) * DM + lkoff;
    const unsigned short* pb = Whb + woff + (size_t)(n0 + lrow) * DM + lkoff;
    const unsigned sRowA = (unsigned)(lrow * (HST2 * 2) + lkoff * 2);
    const unsigned sRowB = sRowA + AB2;
    const bool doB = (NT == 128) || (lrow < NT);

    float acc[MI][4][4];
    #pragma unroll
    for (int i = 0; i < MI; i++)
        #pragma unroll
        for (int j = 0; j < 4; j++)
            #pragma unroll
            for (int r = 0; r < 4; r++) acc[i][j][r] = 0.f;

    auto issueG = [&](int itx, int st) {
        const int k0 = itx * 32;
        const unsigned sb = sbase + (unsigned)st * GSTG;
        cp16(sb + sRowA,      pa + k0);
        cp16(sb + sRowA + 16, pa + k0 + 8);
        if (doB) {
            cp16(sb + sRowB,      pb + k0);
            cp16(sb + sRowB + 16, pb + k0 + 8);
        }
    };

    issueG(0, 0); cp_commit();
    issueG(1, 1); cp_commit();

    #pragma unroll 1
    for (int it = 0; it < 24; ++it) {
        const int s = it % 3;
        if (it == 23) { cp_wait<0>(); } else { cp_wait<1>(); }
        __syncthreads();
        if (it + 2 < 24) { issueG(it + 2, (it + 2) % 3); cp_commit(); }

        const unsigned bufo = sbase + (unsigned)s * GSTG;
        #pragma unroll
        for (int kh = 0; kh < 2; ++kh) {
            unsigned bh[4][2];
            #pragma unroll
            for (int ntp = 0; ntp < 2; ++ntp) {
                unsigned r[4];
                const int rb = wn * 32 + ntp * 16 + rowB_;
                ldm4(r, bufo + AB2 + (unsigned)((rb * HST2 + kh * 16 + colB_) * 2));
                bh[ntp*2][0] = r[0]; bh[ntp*2][1] = r[1];
                bh[ntp*2+1][0] = r[2]; bh[ntp*2+1][1] = r[3];
            }
            #pragma unroll
            for (int mi = 0; mi < MI; ++mi) {
                const int ra = wm * (MI * 16) + mi * 16 + rowA_;
                unsigned ah[4];
                ldm4(ah, bufo + (unsigned)((ra * HST2 + kh * 16 + colA_) * 2));
                #pragma unroll
                for (int ni = 0; ni < 4; ++ni)
                    mma16h(acc[mi][ni], ah[0], ah[1], ah[2], ah[3], bh[ni][0], bh[ni][1]);
            }
        }
    }

    // ---- epilogue ----
    #pragma unroll
    for (int mi = 0; mi < MI; ++mi) {
        const int row = m0 + wm * (MI * 16) + mi * 16 + g;
        #pragma unroll
        for (int ni = 0; ni < 4; ++ni) {
            const int col = n0 + wn * 32 + ni * 8 + c * 2;
            float2 bv = *(const float2*)(bias + col);
            float v0 = acc[mi][ni][0] + bv.x;
            float v1 = acc[mi][ni][1] + bv.y;
            float v2 = acc[mi][ni][2] + bv.x;
            float v3 = acc[mi][ni][3] + bv.y;
            if (MODE == 0) {
                const int bb = row >> 11;
                const int t  = row & 2047;
                const int hd = col >> 6;
                const int d  = col & 63;
                const size_t a0 = (size_t)z * ZSZ + ((size_t)(bb * NH + hd) * TT + t) * DH + d;
                const float sc = (z == 0) ? QSCALE : 1.0f;
                *(unsigned*)(ChB + a0)          = packh2(v0 * sc, v1 * sc);
                *(unsigned*)(ChB + a0 + 8 * DH) = packh2(v2 * sc, v3 * sc);
            } else {
                *(float2*)(outF + (size_t)row * DM + col)       = make_float2(v0, v1);
                *(float2*)(outF + (size_t)(row + 8) * DM + col) = make_float2(v2, v3);
            }
        }
    }
}
#define GSMEM_QKV  (3*(AB2 + 128*HST2*2))   // 61440
#define GSMEM_PROJ (3*(AB2 + 64*HST2*2))    // 46080

// ---------------------------------------------------------------------------
// Flash attention. QK^T fp16 x1; softmax fully in half2 domain (HMNMX2 tree,
// packed (lo,hi) SHFL reduce, HSUB2, ex2.f16x2); row sums via ones-column mma;
// PV fp16 P x fp16 V single. Persistent snake. y as fp16 single.
// ---------------------------------------------------------------------------
#define AKVS 72
#define AARR 9216                  // 64 * 72 * 2 bytes
#define ASTG (2*AARR)              // Kh, Vh = 18432
#define A_KH 0
#define A_VH AARR
#define ASMEM (3*ASTG)             // 55296
#define APERS 296
#define AITEMS 768                 // 16 q-blocks * 48 bh
#define ONESH2 0x3C003C00u

__global__ __launch_bounds__(256, 2)
void attn_bf(float* __restrict__ dummy)
{
    extern __shared__ __align__(16) char asmz[];
    const unsigned uS = s2u(asmz);

    const int tid  = threadIdx.x;
    const int lane = tid & 31;
    const int wid  = tid >> 5;       // 0..7
    const int g  = lane >> 2;
    const int c  = lane & 3;
    const int kblk = blockIdx.x;     // 0..295

    const int rowB_ = (lane & 7) + ((lane >> 4) & 1) * 8;
    const int colB_ = ((lane >> 3) & 1) * 8;
    const int vkey_ = lane & 15;
    const int vd_   = (lane >> 4) * 8;

    #pragma unroll 1
    for (int p = 0; p < 3; ++p) {
        const int j = p * APERS + ((p & 1) ? (APERS - 1 - kblk) : kblk);
        if (j >= AITEMS) continue;
        const int qb = 15 - (j / 48);    // descending cost order
        const int bh = j % 48;

        // ---- Q fragments: raw fp16 bits, already scaled ----
        const unsigned short* qp = g_h3 + ((size_t)bh * TT + qb * 128 + wid * 16) * DH;
        unsigned qf[4][4];
        #pragma unroll
        for (int kc = 0; kc < 4; ++kc) {
            #pragma unroll
            for (int jj = 0; jj < 4; ++jj) {
                const int row = g + (jj & 1) * 8;
                const int col = kc * 16 + 2 * c + (jj >> 1) * 8;
                qf[kc][jj] = *(const unsigned*)(qp + (size_t)row * DH + col);
            }
        }

        float o[8][4];
        #pragma unroll
        for (int i = 0; i < 8; ++i)
            #pragma unroll
            for (int jj = 0; jj < 4; ++jj) o[i][jj] = 0.f;
        // running max as packed half2 (lo-group, hi-group)
        __half2 m_run = __floats2half2_rn(-60000.f, -60000.f);
        float l_lo = 0.f, l_hi = 0.f;

        const unsigned short* kh_b = g_h3 + ZSZ     + (size_t)bh * TT * DH;
        const unsigned short* vh_b = g_h3 + 2 * ZSZ + (size_t)bh * TT * DH;

        const int row_lo = qb * 128 + wid * 16 + g;
        const int row_hi = row_lo + 8;
        const int nkb = 2 * qb + 2;

        auto issue = [&](int kb, int st) {
            const unsigned sb = uS + (unsigned)st * ASTG;
            const size_t t0 = (size_t)kb * 64 * DH;
            #pragma unroll
            for (int i = 0; i < 2; ++i) {
                const int ch  = tid + i * 256;
                const int row = ch >> 3;
                const int seg = ch & 7;
                const unsigned ro = (unsigned)(row * (AKVS * 2) + seg * 16);
                const size_t go = t0 + (size_t)ch * 8;
                cp16(sb + A_KH + ro, kh_b + go);
                cp16(sb + A_VH + ro, vh_b + go);
            }
        };

        issue(0, 0); cp_commit();
        issue(1, 1); cp_commit();

        #pragma unroll 1
        for (int kb = 0; kb < nkb; ++kb) {
            const int s = kb % 3;
            if (kb == nkb - 1) { cp_wait<0>(); } else { cp_wait<1>(); }
            __syncthreads();
            if (kb + 2 < nkb) { issue(kb + 2, (kb + 2) % 3); cp_commit(); }

            const unsigned sk = uS + (unsigned)s * ASTG;

            // ---- S = Q K^T (fp16 x1) ----
            float sx[8][4];
            #pragma unroll
            for (int i = 0; i < 8; ++i)
                #pragma unroll
                for (int jj = 0; jj < 4; ++jj) sx[i][jj] = 0.f;

            #pragma unroll
            for (int kc = 0; kc < 4; ++kc) {
                #pragma unroll
                for (int ntp = 0; ntp < 4; ++ntp) {
                    const unsigned off = (unsigned)(((ntp * 16 + rowB_) * AKVS + kc * 16 + colB_) * 2);
                    unsigned rh[4];
                    ldm4(rh, sk + A_KH + off);
                    mma16h(sx[ntp * 2],     qf[kc][0], qf[kc][1], qf[kc][2], qf[kc][3], rh[0], rh[1]);
                    mma16h(sx[ntp * 2 + 1], qf[kc][0], qf[kc][1], qf[kc][2], qf[kc][3], rh[2], rh[3]);
                }
            }

            // ---- causal mask (f32; -1e30 converts to -inf f16 below) ----
            if (kb * 64 + 63 > qb * 128 + wid * 16) {
                #pragma unroll
                for (int nt = 0; nt < 8; ++nt) {
                    const int k0 = kb * 64 + nt * 8 + c * 2;
                    if (k0 > row_lo)     sx[nt][0] = -1e30f;
                    if (k0 + 1 > row_lo) sx[nt][1] = -1e30f;
                    if (k0 > row_hi)     sx[nt][2] = -1e30f;
                    if (k0 + 1 > row_hi) sx[nt][3] = -1e30f;
                }
            }

            // ---- softmax in half2 domain ----
            unsigned t0[8], t1[8];
            #pragma unroll
            for (int nt = 0; nt < 8; ++nt) {
                t0[nt] = packh2(sx[nt][0], sx[nt][1]);   // rows-lo, 2 cols
                t1[nt] = packh2(sx[nt][2], sx[nt][3]);   // rows-hi, 2 cols
            }
            // max tree per group (both lanes carry column maxes)
            __half2 r0 = __hmax2(__hmax2(u2h2(t0[0]), u2h2(t0[1])),
                                 __hmax2(u2h2(t0[2]), u2h2(t0[3])));
            r0 = __hmax2(r0, __hmax2(__hmax2(u2h2(t0[4]), u2h2(t0[5])),
                                     __hmax2(u2h2(t0[6]), u2h2(t0[7]))));
            __half2 r1 = __hmax2(__hmax2(u2h2(t1[0]), u2h2(t1[1])),
                                 __hmax2(u2h2(t1[2]), u2h2(t1[3])));
            r1 = __hmax2(r1, __hmax2(__hmax2(u2h2(t1[4]), u2h2(t1[5])),
                                     __hmax2(u2h2(t1[6]), u2h2(t1[7]))));
            __half2 mx = __halves2half2(__hmax(__low2half(r0), __high2half(r0)),
                                        __hmax(__low2half(r1), __high2half(r1)));
            // cross-lane reduce over quad (packed lo&hi together)
            mx = __hmax2(mx, u2h2(__shfl_xor_sync(0xffffffffu, h2u(mx), 1)));
            mx = __hmax2(mx, u2h2(__shfl_xor_sync(0xffffffffu, h2u(mx), 2)));
            const __half2 mn = __hmax2(m_run, mx);
            float2 mrf = __half22float2(m_run);
            float2 mnf = __half22float2(mn);
            const float al0 = ex2(mrf.x - mnf.x);
            const float al1 = ex2(mrf.y - mnf.y);
            m_run = mn;
            const __half2 mn_lo = __half2half2(__low2half(mn));
            const __half2 mn_hi = __half2half2(__high2half(mn));

            unsigned pl2[8], ph2[8];
            #pragma unroll
            for (int nt = 0; nt < 8; ++nt) {
                pl2[nt] = ex2h2(h2u(__hsub2(u2h2(t0[nt]), mn_lo)));
                ph2[nt] = ex2h2(h2u(__hsub2(u2h2(t1[nt]), mn_hi)));
                o[nt][0] *= al0; o[nt][1] *= al0;
                o[nt][2] *= al1; o[nt][3] *= al1;
            }

            // ---- row sums via ones-column mma (exact f32 sum of f16 p) ----
            float ls4[4] = {0.f, 0.f, 0.f, 0.f};
            #pragma unroll
            for (int kc = 0; kc < 4; ++kc)
                mma16h(ls4, pl2[2*kc], ph2[2*kc], pl2[2*kc+1], ph2[2*kc+1], ONESH2, ONESH2);
            l_lo = l_lo * al0 + ls4[0];
            l_hi = l_hi * al1 + ls4[2];

            // ---- O += P V (fp16 P x fp16 V single) ----
            #pragma unroll
            for (int kc = 0; kc < 4; ++kc) {
                const unsigned a0 = pl2[2*kc];
                const unsigned a1 = ph2[2*kc];
                const unsigned a2 = pl2[2*kc+1];
                const unsigned a3 = ph2[2*kc+1];
                #pragma unroll
                for (int ntp = 0; ntp < 4; ++ntp) {
                    const unsigned off =
                        (unsigned)(((kc * 16 + vkey_) * AKVS + ntp * 16 + vd_) * 2);
                    unsigned vh[4];
                    ldm4t(vh, sk + A_VH + off);
                    mma16h(o[ntp * 2],     a0, a1, a2, a3, vh[0], vh[1]);
                    mma16h(o[ntp * 2 + 1], a0, a1, a2, a3, vh[2], vh[3]);
                }
            }
        }

        // ---- epilogue (y as fp16 single) ----
        const float inv_lo = 1.f / l_lo;
        const float inv_hi = 1.f / l_hi;

        const int bbv = bh / NH;
        const int hd  = bh % NH;
        const size_t alo = ((size_t)bbv * TT + row_lo) * DM + hd * DH + 2 * c;
        const size_t ahi = ((size_t)bbv * TT + row_hi) * DM + hd * DH + 2 * c;
        #pragma unroll
        for (int nt = 0; nt < 8; ++nt) {
            *(unsigned*)(g_yh + alo + nt * 8) = packh2(o[nt][0] * inv_lo, o[nt][1] * inv_lo);
            *(unsigned*)(g_yh + ahi + nt * 8) = packh2(o[nt][2] * inv_hi, o[nt][3] * inv_hi);
        }

        __syncthreads();   // protect smem stages before next item's prologue
    }
    (void)dummy;
}

// ---------------------------------------------------------------------------
extern "C" void kernel_launch(void* const* d_in, const int* in_sizes, int n_in,
                              void* d_out, int out_size)
{
    const float* x  = (const float*)d_in[0];
    const float* Wq = (const float*)d_in[1];
    const float* bq = (const float*)d_in[2];
    const float* Wk = (const float*)d_in[3];
    const float* bk = (const float*)d_in[4];
    const float* Wv = (const float*)d_in[5];
    const float* bv = (const float*)d_in[6];
    const float* Wp = (const float*)d_in[7];
    const float* bp = (const float*)d_in[8];
    float* out = (float*)d_out;

    unsigned short *xh, *wh, *h3, *yh;
    cudaGetSymbolAddress((void**)&xh, g_xh);
    cudaGetSymbolAddress((void**)&wh, g_wh);
    cudaGetSymbolAddress((void**)&h3, g_h3);
    cudaGetSymbolAddress((void**)&yh, g_yh);

    cudaFuncSetAttribute(gemm_f16<0>, cudaFuncAttributeMaxDynamicSharedMemorySize, GSMEM_QKV);
    cudaFuncSetAttribute(gemm_f16<1>, cudaFuncAttributeMaxDynamicSharedMemorySize, GSMEM_PROJ);
    cudaFuncSetAttribute(attn_bf, cudaFuncAttributeMaxDynamicSharedMemorySize, ASMEM);

    // pre-pass conversions
    const int n4x = MROWS * DM / 4;
    const int n4w = DM * DM / 4;
    convert_x<<<(n4x + 255) / 256, 256>>>(x, xh, n4x);
    dim3 wgrid((n4w + 255) / 256, 4);
    convert_w4<<<wgrid, 256>>>(Wq, Wk, Wv, Wp, wh, n4w);

    // QKV: z=0 -> Q (scaled), z=1 -> K, z=2 -> V (all fp16 single)
    dim3 qkv_grid(DM / 128, MROWS / 128, 3);
    gemm_f16<0><<<qkv_grid, 256, GSMEM_QKV>>>(xh, wh, bq, bk, bv, h3, nullptr);

    // attention (persistent, load-balanced)
    attn_bf<<<APERS, 256, ASMEM>>>(nullptr);

    // out-proj (BN=64 tiles: 768 blocks -> minimal tail waste; fp32 out)
    dim3 proj_grid(DM / 64, MROWS / 128, 1);
    gemm_f16<1><<<proj_grid, 256, GSMEM_PROJ>>>(yh, wh, bp, bp, bp, nullptr, out);
}